// round 1
// baseline (speedup 1.0000x reference)
#include <cuda_runtime.h>

#define S_LEN 2048
#define DIMN  512
#define NH    8
#define DH    64
#define MTOT  8192   // b*l*s = 2*2*2048
#define NBLH  32     // b*l*h

// Scratch (allocation-free): Q/K/V in (blh, s, dh) layout, inter in (m, e) layout.
__device__ float g_Q[NBLH * S_LEN * DH];
__device__ float g_K[NBLH * S_LEN * DH];
__device__ float g_V[NBLH * S_LEN * DH];
__device__ float g_inter[MTOT * DIMN];

// ---------------------------------------------------------------------------
// NT GEMM: Y[m][e] = sum_d A[m][d] * W[e][d] + bias[e], optional rotary,
// optional scatter to (blh, s, dh) scratch.
// Block tile 64x64, K-tile 32, 256 threads, 4x4 per thread.
// ---------------------------------------------------------------------------
__global__ __launch_bounds__(256)
void gemm_kernel(const float* __restrict__ Aext,
                 const float* __restrict__ W,
                 const float* __restrict__ bias,
                 float* __restrict__ out_ext,
                 int dst_sel,      // 0:g_Q 1:g_K 2:g_V 3:out_ext(row-major)
                 int do_rotary,
                 int src_inter)    // 1: read A from g_inter
{
    __shared__ __align__(16) float As[32][64];
    __shared__ __align__(16) float Bs[32][64];

    const float* A = src_inter ? g_inter : Aext;
    float* dst = (dst_sel == 0) ? g_Q : (dst_sel == 1) ? g_K
               : (dst_sel == 2) ? g_V : out_ext;

    const int tid = threadIdx.x;
    const int tx = tid & 15;      // output col group
    const int ty = tid >> 4;      // output row group
    const int n0 = blockIdx.x * 64;
    const int m0 = blockIdx.y * 64;

    float acc[4][4] = {};

    for (int k0 = 0; k0 < DIMN; k0 += 32) {
        #pragma unroll
        for (int i = 0; i < 2; i++) {
            int q4  = i * 256 + tid;     // 0..511 float4s per operand tile
            int row = q4 >> 3;           // 0..63
            int c4  = q4 & 7;            // 0..7
            float4 av = *(const float4*)(A + (size_t)(m0 + row) * DIMN + k0 + c4 * 4);
            As[c4 * 4 + 0][row] = av.x;
            As[c4 * 4 + 1][row] = av.y;
            As[c4 * 4 + 2][row] = av.z;
            As[c4 * 4 + 3][row] = av.w;
            float4 wv = *(const float4*)(W + (size_t)(n0 + row) * DIMN + k0 + c4 * 4);
            Bs[c4 * 4 + 0][row] = wv.x;
            Bs[c4 * 4 + 1][row] = wv.y;
            Bs[c4 * 4 + 2][row] = wv.z;
            Bs[c4 * 4 + 3][row] = wv.w;
        }
        __syncthreads();
        #pragma unroll
        for (int k = 0; k < 32; k++) {
            float4 a4 = *(const float4*)&As[k][ty * 4];
            float4 b4 = *(const float4*)&Bs[k][tx * 4];
            float av[4] = {a4.x, a4.y, a4.z, a4.w};
            float bv[4] = {b4.x, b4.y, b4.z, b4.w};
            #pragma unroll
            for (int i = 0; i < 4; i++)
                #pragma unroll
                for (int j = 0; j < 4; j++)
                    acc[i][j] += av[i] * bv[j];
        }
        __syncthreads();
    }

    // Epilogue
    const int e0 = n0 + tx * 4;
    float4 b4 = *(const float4*)(bias + e0);
    float bv[4] = {b4.x, b4.y, b4.z, b4.w};

    // rotary invariants for this thread's 4 columns (two adjacent pairs)
    const int   jh   = e0 & (DH - 1);                 // even, 0..60
    const float LNC  = 0.14391156831212787f;          // ln(10000)/64
    const float inv0 = __expf(0.0f) * expf(-(float)jh * LNC);
    const float inv1 = expf(-(float)(jh + 2) * LNC);

    #pragma unroll
    for (int i = 0; i < 4; i++) {
        int m = m0 + ty * 4 + i;
        float v0 = acc[i][0] + bv[0];
        float v1 = acc[i][1] + bv[1];
        float v2 = acc[i][2] + bv[2];
        float v3 = acc[i][3] + bv[3];

        if (do_rotary) {
            float t = (float)(m & (S_LEN - 1));
            float s0, c0, s1, c1;
            sincosf(t * inv0, &s0, &c0);
            sincosf(t * inv1, &s1, &c1);
            float r0 = v0 * c0 - v1 * s0;
            float r1 = v1 * c0 + v0 * s0;
            float r2 = v2 * c1 - v3 * s1;
            float r3 = v3 * c1 + v2 * s1;
            v0 = r0; v1 = r1; v2 = r2; v3 = r3;
        }

        float4 o = make_float4(v0, v1, v2, v3);
        if (dst_sel < 3) {
            int bl   = m >> 11;
            int spos = m & (S_LEN - 1);
            int h    = e0 >> 6;
            int jd   = e0 & (DH - 1);
            *(float4*)&dst[((size_t)(bl * NH + h) * S_LEN + spos) * DH + jd] = o;
        } else {
            *(float4*)&dst[(size_t)m * DIMN + e0] = o;
        }
    }
}

// ---------------------------------------------------------------------------
// Flash attention, causal, fp32. One block = 64 query rows of one (bl,h).
// 256 threads, 4 rows x 4 cols per thread. P stays in registers; PV uses
// __shfl broadcast within the 16-thread row groups.
// ---------------------------------------------------------------------------
__global__ __launch_bounds__(256)
void flash_attn_kernel()
{
    __shared__ __align__(16) float Qt[DH * 64];   // Qt[d][q], pre-scaled
    __shared__ __align__(16) float Kt[DH * 64];   // Kt[d][key]
    __shared__ __align__(16) float Vs[64 * DH];   // Vs[key][d]

    const int blh = blockIdx.y;   // 0..31
    const int qb  = blockIdx.x;   // 0..31
    const float* Qg = g_Q + (size_t)blh * S_LEN * DH;
    const float* Kg = g_K + (size_t)blh * S_LEN * DH;
    const float* Vg = g_V + (size_t)blh * S_LEN * DH;

    const int tid = threadIdx.x;
    const int tx = tid & 15, ty = tid >> 4;
    const float scale = 0.04419417382415922f;  // 1/sqrt(512)

    // Load + transpose Q tile (scaled)
    #pragma unroll
    for (int i = 0; i < 4; i++) {
        int q4  = i * 256 + tid;   // 0..1023
        int row = q4 >> 4;         // 0..63
        int c4  = q4 & 15;         // 0..15
        float4 v = *(const float4*)(Qg + (size_t)(qb * 64 + row) * DH + c4 * 4);
        Qt[(c4 * 4 + 0) * 64 + row] = v.x * scale;
        Qt[(c4 * 4 + 1) * 64 + row] = v.y * scale;
        Qt[(c4 * 4 + 2) * 64 + row] = v.z * scale;
        Qt[(c4 * 4 + 3) * 64 + row] = v.w * scale;
    }

    float m_run[4], l_run[4], acc[4][4];
    #pragma unroll
    for (int i = 0; i < 4; i++) {
        m_run[i] = -1e30f; l_run[i] = 0.f;
        #pragma unroll
        for (int j = 0; j < 4; j++) acc[i][j] = 0.f;
    }

    for (int kb = 0; kb <= qb; kb++) {
        __syncthreads();   // Q visible (1st iter) / prev PV done before K/V overwrite
        #pragma unroll
        for (int i = 0; i < 4; i++) {
            int q4  = i * 256 + tid;
            int row = q4 >> 4;
            int c4  = q4 & 15;
            float4 kv = *(const float4*)(Kg + (size_t)(kb * 64 + row) * DH + c4 * 4);
            Kt[(c4 * 4 + 0) * 64 + row] = kv.x;
            Kt[(c4 * 4 + 1) * 64 + row] = kv.y;
            Kt[(c4 * 4 + 2) * 64 + row] = kv.z;
            Kt[(c4 * 4 + 3) * 64 + row] = kv.w;
            float4 vv = *(const float4*)(Vg + (size_t)(kb * 64 + row) * DH + c4 * 4);
            *(float4*)&Vs[row * DH + c4 * 4] = vv;
        }
        __syncthreads();

        // S = (scaled Q) K^T
        float s[4][4] = {};
        #pragma unroll
        for (int k = 0; k < DH; k++) {
            float4 a4 = *(const float4*)&Qt[k * 64 + ty * 4];
            float4 b4 = *(const float4*)&Kt[k * 64 + tx * 4];
            float av[4] = {a4.x, a4.y, a4.z, a4.w};
            float bvv[4] = {b4.x, b4.y, b4.z, b4.w};
            #pragma unroll
            for (int i = 0; i < 4; i++)
                #pragma unroll
                for (int j = 0; j < 4; j++)
                    s[i][j] += av[i] * bvv[j];
        }

        // Causal mask (only on diagonal block)
        if (kb == qb) {
            #pragma unroll
            for (int i = 0; i < 4; i++)
                #pragma unroll
                for (int j = 0; j < 4; j++)
                    if (tx * 4 + j > ty * 4 + i) s[i][j] = -1e30f;
        }

        // Online softmax
        float p[4][4];
        #pragma unroll
        for (int i = 0; i < 4; i++) {
            float mx = fmaxf(fmaxf(s[i][0], s[i][1]), fmaxf(s[i][2], s[i][3]));
            #pragma unroll
            for (int off = 8; off >= 1; off >>= 1)
                mx = fmaxf(mx, __shfl_xor_sync(0xffffffffu, mx, off));
            float mn = fmaxf(m_run[i], mx);
            float al = expf(m_run[i] - mn);
            m_run[i] = mn;
            float sum = 0.f;
            #pragma unroll
            for (int j = 0; j < 4; j++) {
                p[i][j] = expf(s[i][j] - mn);
                sum += p[i][j];
            }
            #pragma unroll
            for (int off = 8; off >= 1; off >>= 1)
                sum += __shfl_xor_sync(0xffffffffu, sum, off);
            l_run[i] = l_run[i] * al + sum;
            #pragma unroll
            for (int j = 0; j < 4; j++) acc[i][j] *= al;
        }

        // O += P @ V  (broadcast P across the 16-lane row group)
        #pragma unroll
        for (int k4 = 0; k4 < 16; k4++) {
            int src = (tid & 16) | k4;  // owner lane of key column group k4
            #pragma unroll
            for (int j2 = 0; j2 < 4; j2++) {
                int k = k4 * 4 + j2;
                float4 v4 = *(const float4*)&Vs[k * DH + tx * 4];
                float vv[4] = {v4.x, v4.y, v4.z, v4.w};
                float pk[4];
                #pragma unroll
                for (int i = 0; i < 4; i++)
                    pk[i] = __shfl_sync(0xffffffffu, p[i][j2], src);
                #pragma unroll
                for (int i = 0; i < 4; i++)
                    #pragma unroll
                    for (int j = 0; j < 4; j++)
                        acc[i][j] += pk[i] * vv[j];
            }
        }
    }

    // Write inter in (m, h*dh) row-major
    const int bl = blh >> 3, h = blh & 7;
    #pragma unroll
    for (int i = 0; i < 4; i++) {
        int q = qb * 64 + ty * 4 + i;
        float inv = 1.f / l_run[i];
        float4 o = make_float4(acc[i][0] * inv, acc[i][1] * inv,
                               acc[i][2] * inv, acc[i][3] * inv);
        *(float4*)&g_inter[((size_t)(bl * S_LEN + q)) * DIMN + h * DH + tx * 4] = o;
    }
}

// ---------------------------------------------------------------------------
extern "C" void kernel_launch(void* const* d_in, const int* in_sizes, int n_in,
                              void* d_out, int out_size)
{
    const float* x  = (const float*)d_in[0];
    const float* Wq = (const float*)d_in[1];
    const float* bq = (const float*)d_in[2];
    const float* Wk = (const float*)d_in[3];
    const float* bk = (const float*)d_in[4];
    const float* Wv = (const float*)d_in[5];
    const float* bv = (const float*)d_in[6];
    const float* Wo = (const float*)d_in[7];
    const float* bo = (const float*)d_in[8];
    float* out = (float*)d_out;

    dim3 gthr(256);
    dim3 ggrd(DIMN / 64, MTOT / 64);

    // Reference quirks: q = rotary(x@Wq^T), k = rotary(x@Wv^T), v = x@Wk^T
    gemm_kernel<<<ggrd, gthr>>>(x, Wq, bq, nullptr, 0, 1, 0);  // -> g_Q (rotary)
    gemm_kernel<<<ggrd, gthr>>>(x, Wv, bv, nullptr, 1, 1, 0);  // -> g_K (rotary, Wv!)
    gemm_kernel<<<ggrd, gthr>>>(x, Wk, bk, nullptr, 2, 0, 0);  // -> g_V (Wk!)

    flash_attn_kernel<<<dim3(S_LEN / 64, NBLH), 256>>>();

    gemm_kernel<<<ggrd, gthr>>>(nullptr, Wo, bo, out, 3, 0, 1); // inter @ Wo^T + bo
}

// round 2
// speedup vs baseline: 1.4225x; 1.4225x over previous
#include <cuda_runtime.h>

#define S_LEN 2048
#define DIMN  512
#define NH    8
#define DH    64
#define MTOT  8192   // b*l*s = 2*2*2048
#define NBLH  32     // b*l*h

// Scratch (allocation-free)
__device__ float g_Q[NBLH * S_LEN * DH];
__device__ float g_K[NBLH * S_LEN * DH];
__device__ float g_V[NBLH * S_LEN * DH];
__device__ float g_inter[MTOT * DIMN];

// ---------------------------------------------------------------------------
// f32x2 packed-math helpers (Blackwell sm_100+)
// ---------------------------------------------------------------------------
__device__ __forceinline__ unsigned long long dup2(float s) {
    unsigned long long r;
    asm("mov.b64 %0, {%1, %1};" : "=l"(r) : "f"(s));
    return r;
}
__device__ __forceinline__ unsigned long long pk2(float x, float y) {
    unsigned long long r;
    asm("mov.b64 %0, {%1, %2};" : "=l"(r) : "f"(x), "f"(y));
    return r;
}
__device__ __forceinline__ void fma2(unsigned long long &d,
                                     unsigned long long a,
                                     unsigned long long b) {
    asm("fma.rn.f32x2 %0, %1, %2, %0;" : "+l"(d) : "l"(a), "l"(b));
}
__device__ __forceinline__ void mul2s(unsigned long long &d, float s) {
    asm("mul.rn.f32x2 %0, %0, %1;" : "+l"(d) : "l"(dup2(s)));
}
__device__ __forceinline__ float2 up2(unsigned long long u) {
    float2 v;
    asm("mov.b64 {%0, %1}, %2;" : "=f"(v.x), "=f"(v.y) : "l"(u));
    return v;
}

// ---------------------------------------------------------------------------
// NT GEMM: Y[m][e] = sum_d A[m][d]*W[e][d] + bias[e]; 128x128 tile, kt=32,
// 256 threads, 8x8 per thread, f32x2 math, XOR-swizzled transpose staging.
// ---------------------------------------------------------------------------
__global__ __launch_bounds__(256, 2)
void gemm_kernel(const float* __restrict__ Aext,
                 const float* __restrict__ W,
                 const float* __restrict__ bias,
                 float* __restrict__ out_ext,
                 int dst_sel,      // 0:g_Q 1:g_K 2:g_V 3:out_ext(row-major)
                 int do_rotary,
                 int src_inter)
{
    __shared__ __align__(16) float As[32 * 128];
    __shared__ __align__(16) float Bs[32 * 128];

    const float* A = src_inter ? g_inter : Aext;
    float* dst = (dst_sel == 0) ? g_Q : (dst_sel == 1) ? g_K
               : (dst_sel == 2) ? g_V : out_ext;

    const int tid = threadIdx.x;
    const int tx = tid & 15;          // 8 output cols
    const int ty = tid >> 4;          // 8 output rows
    const int n0 = blockIdx.x * 128;
    const int m0 = blockIdx.y * 128;

    unsigned long long acc[8][4] = {};   // 8 rows x 4 col-pairs

    for (int k0 = 0; k0 < DIMN; k0 += 32) {
        // Stage: coalesced global float4 over k, swizzled transpose into [k][m]
        #pragma unroll
        for (int i = 0; i < 4; i++) {
            int idx = i * 256 + tid;          // 0..1023
            int m   = idx >> 3;               // 0..127
            int c4  = idx & 7;                // k-group (k>>2)
            int base = ((((m >> 2) ^ c4) << 2) | (m & 3));
            float4 av = *(const float4*)(A + (size_t)(m0 + m) * DIMN + k0 + c4 * 4);
            As[(c4 * 4 + 0) * 128 + base] = av.x;
            As[(c4 * 4 + 1) * 128 + base] = av.y;
            As[(c4 * 4 + 2) * 128 + base] = av.z;
            As[(c4 * 4 + 3) * 128 + base] = av.w;
            float4 wv = *(const float4*)(W + (size_t)(n0 + m) * DIMN + k0 + c4 * 4);
            Bs[(c4 * 4 + 0) * 128 + base] = wv.x;
            Bs[(c4 * 4 + 1) * 128 + base] = wv.y;
            Bs[(c4 * 4 + 2) * 128 + base] = wv.z;
            Bs[(c4 * 4 + 3) * 128 + base] = wv.w;
        }
        __syncthreads();

        #pragma unroll 8
        for (int k = 0; k < 32; k++) {
            int c = k >> 2;
            float4 a0 = *(const float4*)&As[k * 128 + (((2 * ty)     ^ c) << 2)];
            float4 a1 = *(const float4*)&As[k * 128 + (((2 * ty + 1) ^ c) << 2)];
            float4 b0 = *(const float4*)&Bs[k * 128 + (((2 * tx)     ^ c) << 2)];
            float4 b1 = *(const float4*)&Bs[k * 128 + (((2 * tx + 1) ^ c) << 2)];
            unsigned long long bp0 = pk2(b0.x, b0.y);
            unsigned long long bp1 = pk2(b0.z, b0.w);
            unsigned long long bp2 = pk2(b1.x, b1.y);
            unsigned long long bp3 = pk2(b1.z, b1.w);
            float av[8] = {a0.x, a0.y, a0.z, a0.w, a1.x, a1.y, a1.z, a1.w};
            #pragma unroll
            for (int i = 0; i < 8; i++) {
                unsigned long long ad = dup2(av[i]);
                fma2(acc[i][0], ad, bp0);
                fma2(acc[i][1], ad, bp1);
                fma2(acc[i][2], ad, bp2);
                fma2(acc[i][3], ad, bp3);
            }
        }
        __syncthreads();
    }

    // ---- Epilogue ----
    const int e0 = n0 + tx * 8;
    float4 bq0 = *(const float4*)(bias + e0);
    float4 bq1 = *(const float4*)(bias + e0 + 4);
    float bvv[8] = {bq0.x, bq0.y, bq0.z, bq0.w, bq1.x, bq1.y, bq1.z, bq1.w};

    const int   jh0 = e0 & (DH - 1);
    const float LNC = 0.14391156831212787f;   // ln(10000)/64
    float invf[4];
    #pragma unroll
    for (int p = 0; p < 4; p++) invf[p] = expf(-(float)(jh0 + 2 * p) * LNC);

    #pragma unroll
    for (int i = 0; i < 8; i++) {
        int m = m0 + ty * 8 + i;
        float v[8];
        #pragma unroll
        for (int j = 0; j < 4; j++) {
            float2 t = up2(acc[i][j]);
            v[2 * j]     = t.x + bvv[2 * j];
            v[2 * j + 1] = t.y + bvv[2 * j + 1];
        }
        if (do_rotary) {
            float t = (float)(m & (S_LEN - 1));
            #pragma unroll
            for (int p = 0; p < 4; p++) {
                float sp, cp;
                sincosf(t * invf[p], &sp, &cp);
                float x0 = v[2 * p], x1 = v[2 * p + 1];
                v[2 * p]     = x0 * cp - x1 * sp;
                v[2 * p + 1] = x1 * cp + x0 * sp;
            }
        }
        float4 o0 = make_float4(v[0], v[1], v[2], v[3]);
        float4 o1 = make_float4(v[4], v[5], v[6], v[7]);
        if (dst_sel < 3) {
            int bl   = m >> 11;
            int spos = m & (S_LEN - 1);
            int h    = e0 >> 6;
            int jd   = e0 & (DH - 1);
            float* base = &dst[((size_t)(bl * NH + h) * S_LEN + spos) * DH + jd];
            *(float4*)(base)     = o0;
            *(float4*)(base + 4) = o1;
        } else {
            float* base = &dst[(size_t)m * DIMN + e0];
            *(float4*)(base)     = o0;
            *(float4*)(base + 4) = o1;
        }
    }
}

// ---------------------------------------------------------------------------
// Flash attention, causal, fp32, f32x2 math. 64q x 64k tile, 256 threads,
// 4x4 per thread. P routed through smem (reuses Kt buffer) — no PV shuffles.
// Heavy blocks (large qb) scheduled first.
// ---------------------------------------------------------------------------
__global__ __launch_bounds__(256, 2)
void flash_attn_kernel()
{
    __shared__ __align__(16) float Qt[64 * 64];   // Q^T [d][q], swizzled, pre-scaled
    __shared__ __align__(16) float KtP[64 * 64];  // K^T [d][k] swizzled -> then P[q][k]
    __shared__ __align__(16) float Vs[64 * 64];   // V [k][d]

    const int blh = blockIdx.y;
    const int qb  = gridDim.x - 1 - blockIdx.x;   // heavy-first
    const float* Qg = g_Q + (size_t)blh * S_LEN * DH;
    const float* Kg = g_K + (size_t)blh * S_LEN * DH;
    const float* Vg = g_V + (size_t)blh * S_LEN * DH;

    const int tid = threadIdx.x;
    const int tx = tid & 15, ty = tid >> 4;
    const float scale = 0.04419417382415922f;     // 1/sqrt(512)

    // Stage Q transposed + swizzled, pre-scaled
    #pragma unroll
    for (int i = 0; i < 4; i++) {
        int idx = i * 256 + tid;
        int q   = idx >> 4;           // 0..63
        int c4  = idx & 15;           // d-group (d>>2)
        float4 v = *(const float4*)(Qg + (size_t)(qb * 64 + q) * DH + c4 * 4);
        int base = ((((q >> 2) ^ c4) << 2) | (q & 3));
        Qt[(c4 * 4 + 0) * 64 + base] = v.x * scale;
        Qt[(c4 * 4 + 1) * 64 + base] = v.y * scale;
        Qt[(c4 * 4 + 2) * 64 + base] = v.z * scale;
        Qt[(c4 * 4 + 3) * 64 + base] = v.w * scale;
    }

    unsigned long long acc[4][2] = {};
    float m_run[4], l_run[4];
    #pragma unroll
    for (int i = 0; i < 4; i++) { m_run[i] = -1e30f; l_run[i] = 0.f; }

    for (int kb = 0; kb <= qb; kb++) {
        __syncthreads();   // P reads of prev iter done; Q visible on iter 0
        #pragma unroll
        for (int i = 0; i < 4; i++) {
            int idx = i * 256 + tid;
            int r   = idx >> 4;
            int c4  = idx & 15;
            float4 kv = *(const float4*)(Kg + (size_t)(kb * 64 + r) * DH + c4 * 4);
            int base = ((((r >> 2) ^ c4) << 2) | (r & 3));
            KtP[(c4 * 4 + 0) * 64 + base] = kv.x;
            KtP[(c4 * 4 + 1) * 64 + base] = kv.y;
            KtP[(c4 * 4 + 2) * 64 + base] = kv.z;
            KtP[(c4 * 4 + 3) * 64 + base] = kv.w;
            float4 vv = *(const float4*)(Vg + (size_t)(kb * 64 + r) * DH + c4 * 4);
            *(float4*)&Vs[r * 64 + c4 * 4] = vv;
        }
        __syncthreads();

        // S = (scaled Q) K^T
        unsigned long long s2[4][2] = {};
        #pragma unroll 4
        for (int k = 0; k < DH; k++) {
            int c = (k >> 2) & 15;
            float4 a4 = *(const float4*)&Qt[k * 64 + ((ty ^ c) << 2)];
            float4 b4 = *(const float4*)&KtP[k * 64 + ((tx ^ c) << 2)];
            unsigned long long b0 = pk2(b4.x, b4.y);
            unsigned long long b1 = pk2(b4.z, b4.w);
            unsigned long long a;
            a = dup2(a4.x); fma2(s2[0][0], a, b0); fma2(s2[0][1], a, b1);
            a = dup2(a4.y); fma2(s2[1][0], a, b0); fma2(s2[1][1], a, b1);
            a = dup2(a4.z); fma2(s2[2][0], a, b0); fma2(s2[2][1], a, b1);
            a = dup2(a4.w); fma2(s2[3][0], a, b0); fma2(s2[3][1], a, b1);
        }

        float s[4][4];
        #pragma unroll
        for (int i = 0; i < 4; i++) {
            float2 t0 = up2(s2[i][0]), t1 = up2(s2[i][1]);
            s[i][0] = t0.x; s[i][1] = t0.y; s[i][2] = t1.x; s[i][3] = t1.y;
        }

        if (kb == qb) {
            #pragma unroll
            for (int i = 0; i < 4; i++)
                #pragma unroll
                for (int j = 0; j < 4; j++)
                    if (tx * 4 + j > ty * 4 + i) s[i][j] = -1e30f;
        }

        // Online softmax (register-resident)
        float p[4][4];
        #pragma unroll
        for (int i = 0; i < 4; i++) {
            float mx = fmaxf(fmaxf(s[i][0], s[i][1]), fmaxf(s[i][2], s[i][3]));
            #pragma unroll
            for (int off = 8; off >= 1; off >>= 1)
                mx = fmaxf(mx, __shfl_xor_sync(0xffffffffu, mx, off));
            float mn = fmaxf(m_run[i], mx);
            float al = __expf(m_run[i] - mn);
            m_run[i] = mn;
            float sum = 0.f;
            #pragma unroll
            for (int j = 0; j < 4; j++) {
                p[i][j] = __expf(s[i][j] - mn);
                sum += p[i][j];
            }
            #pragma unroll
            for (int off = 8; off >= 1; off >>= 1)
                sum += __shfl_xor_sync(0xffffffffu, sum, off);
            l_run[i] = l_run[i] * al + sum;
            mul2s(acc[i][0], al);
            mul2s(acc[i][1], al);
        }

        __syncthreads();   // all K^T reads done before P overwrites
        #pragma unroll
        for (int i = 0; i < 4; i++)
            *(float4*)&KtP[(ty * 4 + i) * 64 + tx * 4] =
                make_float4(p[i][0], p[i][1], p[i][2], p[i][3]);
        __syncthreads();

        // O += P @ V from smem
        #pragma unroll 4
        for (int k4 = 0; k4 < 16; k4++) {
            float pr[4][4];
            #pragma unroll
            for (int i = 0; i < 4; i++) {
                float4 t = *(const float4*)&KtP[(ty * 4 + i) * 64 + k4 * 4];
                pr[i][0] = t.x; pr[i][1] = t.y; pr[i][2] = t.z; pr[i][3] = t.w;
            }
            #pragma unroll
            for (int j2 = 0; j2 < 4; j2++) {
                int k = k4 * 4 + j2;
                float4 v4 = *(const float4*)&Vs[k * 64 + tx * 4];
                unsigned long long v0 = pk2(v4.x, v4.y);
                unsigned long long v1 = pk2(v4.z, v4.w);
                #pragma unroll
                for (int i = 0; i < 4; i++) {
                    unsigned long long pd = dup2(pr[i][j2]);
                    fma2(acc[i][0], pd, v0);
                    fma2(acc[i][1], pd, v1);
                }
            }
        }
    }

    // Write inter in (m, h*dh) row-major
    const int bl = blh >> 3, h = blh & 7;
    #pragma unroll
    for (int i = 0; i < 4; i++) {
        int q = qb * 64 + ty * 4 + i;
        float inv = 1.f / l_run[i];
        float2 o0 = up2(acc[i][0]), o1 = up2(acc[i][1]);
        float4 o = make_float4(o0.x * inv, o0.y * inv, o1.x * inv, o1.y * inv);
        *(float4*)&g_inter[((size_t)(bl * S_LEN + q)) * DIMN + h * DH + tx * 4] = o;
    }
}

// ---------------------------------------------------------------------------
extern "C" void kernel_launch(void* const* d_in, const int* in_sizes, int n_in,
                              void* d_out, int out_size)
{
    const float* x  = (const float*)d_in[0];
    const float* Wq = (const float*)d_in[1];
    const float* bq = (const float*)d_in[2];
    const float* Wk = (const float*)d_in[3];
    const float* bk = (const float*)d_in[4];
    const float* Wv = (const float*)d_in[5];
    const float* bv = (const float*)d_in[6];
    const float* Wo = (const float*)d_in[7];
    const float* bo = (const float*)d_in[8];
    float* out = (float*)d_out;

    dim3 gthr(256);
    dim3 ggrd(DIMN / 128, MTOT / 128);

    // Reference quirks: q = rotary(x@Wq^T), k = rotary(x@Wv^T), v = x@Wk^T
    gemm_kernel<<<ggrd, gthr>>>(x, Wq, bq, nullptr, 0, 1, 0);  // -> g_Q (rotary)
    gemm_kernel<<<ggrd, gthr>>>(x, Wv, bv, nullptr, 1, 1, 0);  // -> g_K (rotary, Wv!)
    gemm_kernel<<<ggrd, gthr>>>(x, Wk, bk, nullptr, 2, 0, 0);  // -> g_V (Wk!)

    flash_attn_kernel<<<dim3(S_LEN / 64, NBLH), 256>>>();

    gemm_kernel<<<ggrd, gthr>>>(nullptr, Wo, bo, out, 3, 0, 1); // inter @ Wo^T + bo
}

// round 3
// speedup vs baseline: 1.4285x; 1.0042x over previous
#include <cuda_runtime.h>

#define S_LEN 2048
#define DIMN  512
#define NH    8
#define DH    64
#define MTOT  8192   // b*l*s = 2*2*2048
#define NBLH  32     // b*l*h

// Scratch (allocation-free)
__device__ float g_Q[NBLH * S_LEN * DH];
__device__ float g_K[NBLH * S_LEN * DH];
__device__ float g_V[NBLH * S_LEN * DH];
__device__ float g_inter[MTOT * DIMN];

// ---------------------------------------------------------------------------
// f32x2 packed-math helpers (Blackwell sm_100+)
// ---------------------------------------------------------------------------
__device__ __forceinline__ unsigned long long dup2(float s) {
    unsigned long long r;
    asm("mov.b64 %0, {%1, %1};" : "=l"(r) : "f"(s));
    return r;
}
__device__ __forceinline__ unsigned long long pk2(float x, float y) {
    unsigned long long r;
    asm("mov.b64 %0, {%1, %2};" : "=l"(r) : "f"(x), "f"(y));
    return r;
}
__device__ __forceinline__ void fma2(unsigned long long &d,
                                     unsigned long long a,
                                     unsigned long long b) {
    asm("fma.rn.f32x2 %0, %1, %2, %0;" : "+l"(d) : "l"(a), "l"(b));
}
__device__ __forceinline__ void mul2s(unsigned long long &d, float s) {
    asm("mul.rn.f32x2 %0, %0, %1;" : "+l"(d) : "l"(dup2(s)));
}
__device__ __forceinline__ float2 up2(unsigned long long u) {
    float2 v;
    asm("mov.b64 {%0, %1}, %2;" : "=f"(v.x), "=f"(v.y) : "l"(u));
    return v;
}

// ---------------------------------------------------------------------------
// NT GEMM: Y[m][e] = sum_d A[m][d]*W[e][d] + bias[e]; 128x128 tile, kt=32,
// 256 threads, 8x8 per thread, f32x2 math, XOR-swizzled transpose staging.
// ---------------------------------------------------------------------------
__global__ __launch_bounds__(256, 2)
void gemm_kernel(const float* __restrict__ Aext,
                 const float* __restrict__ W,
                 const float* __restrict__ bias,
                 float* __restrict__ out_ext,
                 int dst_sel,      // 0:g_Q 1:g_K 2:g_V 3:out_ext(row-major)
                 int do_rotary,
                 int src_inter)
{
    __shared__ __align__(16) float As[32 * 128];
    __shared__ __align__(16) float Bs[32 * 128];

    const float* A = src_inter ? g_inter : Aext;
    float* dst = (dst_sel == 0) ? g_Q : (dst_sel == 1) ? g_K
               : (dst_sel == 2) ? g_V : out_ext;

    const int tid = threadIdx.x;
    const int tx = tid & 15;          // 8 output cols
    const int ty = tid >> 4;          // 8 output rows
    const int n0 = blockIdx.x * 128;
    const int m0 = blockIdx.y * 128;

    unsigned long long acc[8][4] = {};   // 8 rows x 4 col-pairs

    for (int k0 = 0; k0 < DIMN; k0 += 32) {
        // Stage: coalesced global float4 over k, swizzled transpose into [k][m]
        #pragma unroll
        for (int i = 0; i < 4; i++) {
            int idx = i * 256 + tid;          // 0..1023
            int m   = idx >> 3;               // 0..127
            int c4  = idx & 7;                // k-group (k>>2)
            int base = ((((m >> 2) ^ c4) << 2) | (m & 3));
            float4 av = *(const float4*)(A + (size_t)(m0 + m) * DIMN + k0 + c4 * 4);
            As[(c4 * 4 + 0) * 128 + base] = av.x;
            As[(c4 * 4 + 1) * 128 + base] = av.y;
            As[(c4 * 4 + 2) * 128 + base] = av.z;
            As[(c4 * 4 + 3) * 128 + base] = av.w;
            float4 wv = *(const float4*)(W + (size_t)(n0 + m) * DIMN + k0 + c4 * 4);
            Bs[(c4 * 4 + 0) * 128 + base] = wv.x;
            Bs[(c4 * 4 + 1) * 128 + base] = wv.y;
            Bs[(c4 * 4 + 2) * 128 + base] = wv.z;
            Bs[(c4 * 4 + 3) * 128 + base] = wv.w;
        }
        __syncthreads();

        #pragma unroll 8
        for (int k = 0; k < 32; k++) {
            int c = k >> 2;
            float4 a0 = *(const float4*)&As[k * 128 + (((2 * ty)     ^ c) << 2)];
            float4 a1 = *(const float4*)&As[k * 128 + (((2 * ty + 1) ^ c) << 2)];
            float4 b0 = *(const float4*)&Bs[k * 128 + (((2 * tx)     ^ c) << 2)];
            float4 b1 = *(const float4*)&Bs[k * 128 + (((2 * tx + 1) ^ c) << 2)];
            unsigned long long bp0 = pk2(b0.x, b0.y);
            unsigned long long bp1 = pk2(b0.z, b0.w);
            unsigned long long bp2 = pk2(b1.x, b1.y);
            unsigned long long bp3 = pk2(b1.z, b1.w);
            float av[8] = {a0.x, a0.y, a0.z, a0.w, a1.x, a1.y, a1.z, a1.w};
            #pragma unroll
            for (int i = 0; i < 8; i++) {
                unsigned long long ad = dup2(av[i]);
                fma2(acc[i][0], ad, bp0);
                fma2(acc[i][1], ad, bp1);
                fma2(acc[i][2], ad, bp2);
                fma2(acc[i][3], ad, bp3);
            }
        }
        __syncthreads();
    }

    // ---- Epilogue ----
    const int e0 = n0 + tx * 8;
    float4 bq0 = *(const float4*)(bias + e0);
    float4 bq1 = *(const float4*)(bias + e0 + 4);
    float bvv[8] = {bq0.x, bq0.y, bq0.z, bq0.w, bq1.x, bq1.y, bq1.z, bq1.w};

    const int   jh0 = e0 & (DH - 1);
    const float LNC = 0.14391156831212787f;   // ln(10000)/64
    float invf[4];
    #pragma unroll
    for (int p = 0; p < 4; p++) invf[p] = expf(-(float)(jh0 + 2 * p) * LNC);

    #pragma unroll
    for (int i = 0; i < 8; i++) {
        int m = m0 + ty * 8 + i;
        float v[8];
        #pragma unroll
        for (int j = 0; j < 4; j++) {
            float2 t = up2(acc[i][j]);
            v[2 * j]     = t.x + bvv[2 * j];
            v[2 * j + 1] = t.y + bvv[2 * j + 1];
        }
        if (do_rotary) {
            float t = (float)(m & (S_LEN - 1));
            #pragma unroll
            for (int p = 0; p < 4; p++) {
                float sp, cp;
                sincosf(t * invf[p], &sp, &cp);
                float x0 = v[2 * p], x1 = v[2 * p + 1];
                v[2 * p]     = x0 * cp - x1 * sp;
                v[2 * p + 1] = x1 * cp + x0 * sp;
            }
        }
        float4 o0 = make_float4(v[0], v[1], v[2], v[3]);
        float4 o1 = make_float4(v[4], v[5], v[6], v[7]);
        if (dst_sel < 3) {
            int bl   = m >> 11;
            int spos = m & (S_LEN - 1);
            int h    = e0 >> 6;
            int jd   = e0 & (DH - 1);
            float* base = &dst[((size_t)(bl * NH + h) * S_LEN + spos) * DH + jd];
            *(float4*)(base)     = o0;
            *(float4*)(base + 4) = o1;
        } else {
            float* base = &dst[(size_t)m * DIMN + e0];
            *(float4*)(base)     = o0;
            *(float4*)(base + 4) = o1;
        }
    }
}

// ---------------------------------------------------------------------------
// Flash attention, causal, fp32, f32x2 math. 64q x 64k tile, 256 threads,
// 4x4 per thread. P routed through smem (reuses Kt buffer) — no PV shuffles.
// Heavy blocks (large qb) scheduled first.
// ---------------------------------------------------------------------------
__global__ __launch_bounds__(256, 2)
void flash_attn_kernel()
{
    __shared__ __align__(16) float Qt[64 * 64];   // Q^T [d][q], swizzled, pre-scaled
    __shared__ __align__(16) float KtP[64 * 64];  // K^T [d][k] swizzled -> then P[q][k]
    __shared__ __align__(16) float Vs[64 * 64];   // V [k][d]

    const int blh = blockIdx.y;
    const int qb  = gridDim.x - 1 - blockIdx.x;   // heavy-first
    const float* Qg = g_Q + (size_t)blh * S_LEN * DH;
    const float* Kg = g_K + (size_t)blh * S_LEN * DH;
    const float* Vg = g_V + (size_t)blh * S_LEN * DH;

    const int tid = threadIdx.x;
    const int tx = tid & 15, ty = tid >> 4;
    const float scale = 0.04419417382415922f;     // 1/sqrt(512)

    // Stage Q transposed + swizzled, pre-scaled
    #pragma unroll
    for (int i = 0; i < 4; i++) {
        int idx = i * 256 + tid;
        int q   = idx >> 4;           // 0..63
        int c4  = idx & 15;           // d-group (d>>2)
        float4 v = *(const float4*)(Qg + (size_t)(qb * 64 + q) * DH + c4 * 4);
        int base = ((((q >> 2) ^ c4) << 2) | (q & 3));
        Qt[(c4 * 4 + 0) * 64 + base] = v.x * scale;
        Qt[(c4 * 4 + 1) * 64 + base] = v.y * scale;
        Qt[(c4 * 4 + 2) * 64 + base] = v.z * scale;
        Qt[(c4 * 4 + 3) * 64 + base] = v.w * scale;
    }

    unsigned long long acc[4][2] = {};
    float m_run[4], l_run[4];
    #pragma unroll
    for (int i = 0; i < 4; i++) { m_run[i] = -1e30f; l_run[i] = 0.f; }

    for (int kb = 0; kb <= qb; kb++) {
        __syncthreads();   // P reads of prev iter done; Q visible on iter 0
        #pragma unroll
        for (int i = 0; i < 4; i++) {
            int idx = i * 256 + tid;
            int r   = idx >> 4;
            int c4  = idx & 15;
            float4 kv = *(const float4*)(Kg + (size_t)(kb * 64 + r) * DH + c4 * 4);
            int base = ((((r >> 2) ^ c4) << 2) | (r & 3));
            KtP[(c4 * 4 + 0) * 64 + base] = kv.x;
            KtP[(c4 * 4 + 1) * 64 + base] = kv.y;
            KtP[(c4 * 4 + 2) * 64 + base] = kv.z;
            KtP[(c4 * 4 + 3) * 64 + base] = kv.w;
            float4 vv = *(const float4*)(Vg + (size_t)(kb * 64 + r) * DH + c4 * 4);
            *(float4*)&Vs[r * 64 + c4 * 4] = vv;
        }
        __syncthreads();

        // S = (scaled Q) K^T
        unsigned long long s2[4][2] = {};
        #pragma unroll 4
        for (int k = 0; k < DH; k++) {
            int c = (k >> 2) & 15;
            float4 a4 = *(const float4*)&Qt[k * 64 + ((ty ^ c) << 2)];
            float4 b4 = *(const float4*)&KtP[k * 64 + ((tx ^ c) << 2)];
            unsigned long long b0 = pk2(b4.x, b4.y);
            unsigned long long b1 = pk2(b4.z, b4.w);
            unsigned long long a;
            a = dup2(a4.x); fma2(s2[0][0], a, b0); fma2(s2[0][1], a, b1);
            a = dup2(a4.y); fma2(s2[1][0], a, b0); fma2(s2[1][1], a, b1);
            a = dup2(a4.z); fma2(s2[2][0], a, b0); fma2(s2[2][1], a, b1);
            a = dup2(a4.w); fma2(s2[3][0], a, b0); fma2(s2[3][1], a, b1);
        }

        float s[4][4];
        #pragma unroll
        for (int i = 0; i < 4; i++) {
            float2 t0 = up2(s2[i][0]), t1 = up2(s2[i][1]);
            s[i][0] = t0.x; s[i][1] = t0.y; s[i][2] = t1.x; s[i][3] = t1.y;
        }

        if (kb == qb) {
            #pragma unroll
            for (int i = 0; i < 4; i++)
                #pragma unroll
                for (int j = 0; j < 4; j++)
                    if (tx * 4 + j > ty * 4 + i) s[i][j] = -1e30f;
        }

        // Online softmax (register-resident)
        float p[4][4];
        #pragma unroll
        for (int i = 0; i < 4; i++) {
            float mx = fmaxf(fmaxf(s[i][0], s[i][1]), fmaxf(s[i][2], s[i][3]));
            #pragma unroll
            for (int off = 8; off >= 1; off >>= 1)
                mx = fmaxf(mx, __shfl_xor_sync(0xffffffffu, mx, off));
            float mn = fmaxf(m_run[i], mx);
            float al = __expf(m_run[i] - mn);
            m_run[i] = mn;
            float sum = 0.f;
            #pragma unroll
            for (int j = 0; j < 4; j++) {
                p[i][j] = __expf(s[i][j] - mn);
                sum += p[i][j];
            }
            #pragma unroll
            for (int off = 8; off >= 1; off >>= 1)
                sum += __shfl_xor_sync(0xffffffffu, sum, off);
            l_run[i] = l_run[i] * al + sum;
            mul2s(acc[i][0], al);
            mul2s(acc[i][1], al);
        }

        __syncthreads();   // all K^T reads done before P overwrites
        #pragma unroll
        for (int i = 0; i < 4; i++)
            *(float4*)&KtP[(ty * 4 + i) * 64 + tx * 4] =
                make_float4(p[i][0], p[i][1], p[i][2], p[i][3]);
        __syncthreads();

        // O += P @ V from smem
        #pragma unroll 4
        for (int k4 = 0; k4 < 16; k4++) {
            float pr[4][4];
            #pragma unroll
            for (int i = 0; i < 4; i++) {
                float4 t = *(const float4*)&KtP[(ty * 4 + i) * 64 + k4 * 4];
                pr[i][0] = t.x; pr[i][1] = t.y; pr[i][2] = t.z; pr[i][3] = t.w;
            }
            #pragma unroll
            for (int j2 = 0; j2 < 4; j2++) {
                int k = k4 * 4 + j2;
                float4 v4 = *(const float4*)&Vs[k * 64 + tx * 4];
                unsigned long long v0 = pk2(v4.x, v4.y);
                unsigned long long v1 = pk2(v4.z, v4.w);
                #pragma unroll
                for (int i = 0; i < 4; i++) {
                    unsigned long long pd = dup2(pr[i][j2]);
                    fma2(acc[i][0], pd, v0);
                    fma2(acc[i][1], pd, v1);
                }
            }
        }
    }

    // Write inter in (m, h*dh) row-major
    const int bl = blh >> 3, h = blh & 7;
    #pragma unroll
    for (int i = 0; i < 4; i++) {
        int q = qb * 64 + ty * 4 + i;
        float inv = 1.f / l_run[i];
        float2 o0 = up2(acc[i][0]), o1 = up2(acc[i][1]);
        float4 o = make_float4(o0.x * inv, o0.y * inv, o1.x * inv, o1.y * inv);
        *(float4*)&g_inter[((size_t)(bl * S_LEN + q)) * DIMN + h * DH + tx * 4] = o;
    }
}

// ---------------------------------------------------------------------------
extern "C" void kernel_launch(void* const* d_in, const int* in_sizes, int n_in,
                              void* d_out, int out_size)
{
    const float* x  = (const float*)d_in[0];
    const float* Wq = (const float*)d_in[1];
    const float* bq = (const float*)d_in[2];
    const float* Wk = (const float*)d_in[3];
    const float* bk = (const float*)d_in[4];
    const float* Wv = (const float*)d_in[5];
    const float* bv = (const float*)d_in[6];
    const float* Wo = (const float*)d_in[7];
    const float* bo = (const float*)d_in[8];
    float* out = (float*)d_out;

    dim3 gthr(256);
    dim3 ggrd(DIMN / 128, MTOT / 128);

    // Reference quirks: q = rotary(x@Wq^T), k = rotary(x@Wv^T), v = x@Wk^T
    gemm_kernel<<<ggrd, gthr>>>(x, Wq, bq, nullptr, 0, 1, 0);  // -> g_Q (rotary)
    gemm_kernel<<<ggrd, gthr>>>(x, Wv, bv, nullptr, 1, 1, 0);  // -> g_K (rotary, Wv!)
    gemm_kernel<<<ggrd, gthr>>>(x, Wk, bk, nullptr, 2, 0, 0);  // -> g_V (Wk!)

    flash_attn_kernel<<<dim3(S_LEN / 64, NBLH), 256>>>();

    gemm_kernel<<<ggrd, gthr>>>(nullptr, Wo, bo, out, 3, 0, 1); // inter @ Wo^T + bo
}

// round 4
// speedup vs baseline: 2.6450x; 1.8516x over previous
#include <cuda_runtime.h>
#include <cuda_bf16.h>

typedef unsigned int u32;

#define S_LEN 2048
#define DIMN  512
#define NH    8
#define DH    64
#define MTOT  8192
#define NBLH  32
#define VROWS 72          // 64 d-rows + ones row (64) + 7 zero pad rows
#define QSCALE 0.04419417382415922f   // 1/sqrt(512)
#define LNC 0.14391156831212787f      // ln(10000)/64

// ---------------------------------------------------------------------------
// Scratch (allocation-free device globals), bf16 hi/lo pairs
// ---------------------------------------------------------------------------
__device__ __align__(16) __nv_bfloat16 g_xhi[MTOT * DIMN],  g_xlo[MTOT * DIMN];
__device__ __align__(16) __nv_bfloat16 g_whi[4 * DIMN * DIMN], g_wlo[4 * DIMN * DIMN];
__device__ __align__(16) __nv_bfloat16 g_qhi[NBLH * S_LEN * DH], g_qlo[NBLH * S_LEN * DH];
__device__ __align__(16) __nv_bfloat16 g_khi[NBLH * S_LEN * DH], g_klo[NBLH * S_LEN * DH];
__device__ __align__(16) __nv_bfloat16 g_vthi[NBLH * VROWS * S_LEN], g_vtlo[NBLH * VROWS * S_LEN];
__device__ __align__(16) __nv_bfloat16 g_ihi[MTOT * DIMN],  g_ilo[MTOT * DIMN];

// ---------------------------------------------------------------------------
// Helpers
// ---------------------------------------------------------------------------
// pack two f32 -> bf16x2 (a -> low half, b -> high half)
__device__ __forceinline__ u32 pkbf(float a, float b) {
    u32 r;
    asm("cvt.rn.bf16x2.f32 %0, %1, %2;" : "=r"(r) : "f"(b), "f"(a));
    return r;
}
__device__ __forceinline__ float bfr(float v) {          // bf16 round-trip
    return __bfloat162float(__float2bfloat16(v));
}
// D += A * B  (m16n8k16 bf16, fp32 accum)
__device__ __forceinline__ void mmab(float* d, const u32* a, u32 b0, u32 b1) {
    asm volatile(
        "mma.sync.aligned.m16n8k16.row.col.f32.bf16.bf16.f32 "
        "{%0,%1,%2,%3}, {%4,%5,%6,%7}, {%8,%9}, {%0,%1,%2,%3};"
        : "+f"(d[0]), "+f"(d[1]), "+f"(d[2]), "+f"(d[3])
        : "r"(a[0]), "r"(a[1]), "r"(a[2]), "r"(a[3]), "r"(b0), "r"(b1));
}

// ---------------------------------------------------------------------------
// Split fp32 -> bf16 hi/lo
// ---------------------------------------------------------------------------
__global__ __launch_bounds__(256)
void split_kernel(const float* __restrict__ src,
                  __nv_bfloat16* __restrict__ hi,
                  __nv_bfloat16* __restrict__ lo)
{
    int i = blockIdx.x * 256 + threadIdx.x;
    float v = src[i];
    __nv_bfloat16 h = __float2bfloat16(v);
    hi[i] = h;
    lo[i] = __float2bfloat16(v - __bfloat162float(h));
}

// Fill V^T rows 64..71 (ones row + zero pad) for all heads
__global__ __launch_bounds__(256)
void vt_ones_kernel()
{
    int idx = blockIdx.x * 256 + threadIdx.x;     // 32*8*2048 total
    int s   = idx & (S_LEN - 1);
    int rr  = (idx >> 11) & 7;
    int blh = idx >> 14;
    size_t a = ((size_t)blh * VROWS + 64 + rr) * S_LEN + s;
    g_vthi[a] = __float2bfloat16(rr == 0 ? 1.0f : 0.0f);
    g_vtlo[a] = __float2bfloat16(0.0f);
}

// ---------------------------------------------------------------------------
// MMA GEMM: Y[m][e] = sum_d A[m][d] * W[e][d] + bias[e]  (split-bf16, 3 MMAs)
// Block tile M=128, N=64, K-step 32. 256 threads = 8 warps, warp owns m16.
// dst_sel: 0 Q(blh,s,dh)  1 K(blh,s,dh)  2 V^T(blh,72,s)  3 fp32 out(m,512)
// ---------------------------------------------------------------------------
__global__ __launch_bounds__(256)
void mma_gemm(const float* __restrict__ bias,
              float* __restrict__ outp,
              int widx, int dst_sel, int do_rot, float scale, int src_sel)
{
    __shared__ __align__(16) __nv_bfloat16 sm[15360];   // 30 KB
    __nv_bfloat16* Ah = sm;              // 128 x 40
    __nv_bfloat16* Al = sm + 5120;
    __nv_bfloat16* Wh = sm + 10240;      // 64 x 40
    __nv_bfloat16* Wl = sm + 12800;

    const __nv_bfloat16* Ahg = src_sel ? g_ihi : g_xhi;
    const __nv_bfloat16* Alg = src_sel ? g_ilo : g_xlo;
    const __nv_bfloat16* Whg = g_whi + (size_t)widx * DIMN * DIMN;
    const __nv_bfloat16* Wlg = g_wlo + (size_t)widx * DIMN * DIMN;

    const int n0 = blockIdx.x * 64;
    const int m0 = blockIdx.y * 128;
    const int tid = threadIdx.x;
    const int warp = tid >> 5, lane = tid & 31;
    const int g = lane >> 2, t = lane & 3;

    float acc[8][4];
    #pragma unroll
    for (int j = 0; j < 8; j++)
        #pragma unroll
        for (int d = 0; d < 4; d++) acc[j][d] = 0.f;

    for (int k0 = 0; k0 < DIMN; k0 += 32) {
        __syncthreads();
        #pragma unroll
        for (int i = 0; i < 2; i++) {           // A tiles: 512 uint4
            int idx = i * 256 + tid;
            int row = idx >> 2, c = idx & 3;
            ((uint4*)Ah)[row * 5 + c] =
                *(const uint4*)(Ahg + (size_t)(m0 + row) * DIMN + k0 + c * 8);
            ((uint4*)Al)[row * 5 + c] =
                *(const uint4*)(Alg + (size_t)(m0 + row) * DIMN + k0 + c * 8);
        }
        {                                        // W tiles: 256 uint4
            int row = tid >> 2, c = tid & 3;
            ((uint4*)Wh)[row * 5 + c] =
                *(const uint4*)(Whg + (size_t)(n0 + row) * DIMN + k0 + c * 8);
            ((uint4*)Wl)[row * 5 + c] =
                *(const uint4*)(Wlg + (size_t)(n0 + row) * DIMN + k0 + c * 8);
        }
        __syncthreads();

        const u32* Ah32 = (const u32*)Ah;
        const u32* Al32 = (const u32*)Al;
        const u32* Wh32 = (const u32*)Wh;
        const u32* Wl32 = (const u32*)Wl;
        const int rb = warp * 16;

        #pragma unroll
        for (int k = 0; k < 2; k++) {
            u32 ah[4], al[4];
            ah[0] = Ah32[(rb + g) * 20 + k * 8 + t];
            ah[1] = Ah32[(rb + g + 8) * 20 + k * 8 + t];
            ah[2] = Ah32[(rb + g) * 20 + k * 8 + 4 + t];
            ah[3] = Ah32[(rb + g + 8) * 20 + k * 8 + 4 + t];
            al[0] = Al32[(rb + g) * 20 + k * 8 + t];
            al[1] = Al32[(rb + g + 8) * 20 + k * 8 + t];
            al[2] = Al32[(rb + g) * 20 + k * 8 + 4 + t];
            al[3] = Al32[(rb + g + 8) * 20 + k * 8 + 4 + t];
            #pragma unroll
            for (int j = 0; j < 8; j++) {
                u32 off = (8 * j + g) * 20 + k * 8 + t;
                u32 b0h = Wh32[off], b1h = Wh32[off + 4];
                u32 b0l = Wl32[off], b1l = Wl32[off + 4];
                mmab(acc[j], ah, b0h, b1h);
                mmab(acc[j], ah, b0l, b1l);
                mmab(acc[j], al, b0h, b1h);
            }
        }
    }

    // ---- Epilogue ----
    const int rb = warp * 16;

    if (dst_sel == 2) {
        // V^T: transpose via smem (two passes: hi then lo)
        __nv_bfloat16* T = sm;   // 64 x 136
        const int bl = m0 >> 11, hh = n0 >> 6;
        const int s0 = m0 & (S_LEN - 1);
        #pragma unroll
        for (int pass = 0; pass < 2; pass++) {
            __syncthreads();
            #pragma unroll
            for (int j = 0; j < 8; j++) {
                int cl0 = 8 * j + 2 * t;
                float b0 = bias[n0 + cl0], b1 = bias[n0 + cl0 + 1];
                float v00 = acc[j][0] + b0, v01 = acc[j][1] + b1;
                float v10 = acc[j][2] + b0, v11 = acc[j][3] + b1;
                float e00, e01, e10, e11;
                if (pass == 0) { e00 = v00; e01 = v01; e10 = v10; e11 = v11; }
                else { e00 = v00 - bfr(v00); e01 = v01 - bfr(v01);
                       e10 = v10 - bfr(v10); e11 = v11 - bfr(v11); }
                T[(cl0)     * 136 + rb + g]     = __float2bfloat16(e00);
                T[(cl0 + 1) * 136 + rb + g]     = __float2bfloat16(e01);
                T[(cl0)     * 136 + rb + g + 8] = __float2bfloat16(e10);
                T[(cl0 + 1) * 136 + rb + g + 8] = __float2bfloat16(e11);
            }
            __syncthreads();
            __nv_bfloat16* dst = pass ? g_vtlo : g_vthi;
            size_t base = ((size_t)(bl * NH + hh)) * VROWS * S_LEN + s0;
            #pragma unroll
            for (int w8 = 0; w8 < 4; w8++) {
                int idx = w8 * 256 + tid;        // 64 rows x 16 uint4
                int row = idx >> 4, c8 = idx & 15;
                *(uint4*)(dst + base + (size_t)row * S_LEN + c8 * 8) =
                    *(const uint4*)(T + row * 136 + c8 * 8);
            }
        }
        return;
    }

    #pragma unroll
    for (int j = 0; j < 8; j++) {
        int c0 = n0 + 8 * j + 2 * t;
        float b0 = bias[c0], b1 = bias[c0 + 1];
        float v00 = acc[j][0] + b0, v01 = acc[j][1] + b1;
        float v10 = acc[j][2] + b0, v11 = acc[j][3] + b1;
        int r0 = m0 + rb + g, r1 = r0 + 8;
        if (do_rot) {
            float invf = expf(-(float)(c0 & (DH - 1)) * LNC);
            float sn, cs;
            sincosf((float)(r0 & (S_LEN - 1)) * invf, &sn, &cs);
            float x0 = v00, x1 = v01;
            v00 = x0 * cs - x1 * sn;  v01 = x1 * cs + x0 * sn;
            sincosf((float)(r1 & (S_LEN - 1)) * invf, &sn, &cs);
            x0 = v10; x1 = v11;
            v10 = x0 * cs - x1 * sn;  v11 = x1 * cs + x0 * sn;
        }
        v00 *= scale; v01 *= scale; v10 *= scale; v11 *= scale;

        if (dst_sel == 3) {
            float2 o0 = make_float2(v00, v01);
            float2 o1 = make_float2(v10, v11);
            *(float2*)(outp + (size_t)r0 * DIMN + c0) = o0;
            *(float2*)(outp + (size_t)r1 * DIMN + c0) = o1;
        } else {
            u32* dh = (u32*)(dst_sel ? g_khi : g_qhi);
            u32* dl = (u32*)(dst_sel ? g_klo : g_qlo);
            int hh = c0 >> 6, jd = c0 & (DH - 1);
            int bl = m0 >> 11;
            size_t i0 = (((size_t)(bl * NH + hh) * S_LEN + (r0 & (S_LEN - 1))) * DH + jd) >> 1;
            size_t i1 = (((size_t)(bl * NH + hh) * S_LEN + (r1 & (S_LEN - 1))) * DH + jd) >> 1;
            float h00 = bfr(v00), h01 = bfr(v01), h10 = bfr(v10), h11 = bfr(v11);
            dh[i0] = pkbf(h00, h01);
            dl[i0] = pkbf(v00 - h00, v01 - h01);
            dh[i1] = pkbf(h10, h11);
            dl[i1] = pkbf(v10 - h10, v11 - h11);
        }
    }
}

// ---------------------------------------------------------------------------
// Flash attention via HMMA, causal, no-max softmax, ones-column row sums.
// Block = 128 q rows of one (bl,h); 256 threads = 8 warps, warp owns m16.
// ---------------------------------------------------------------------------
__global__ __launch_bounds__(256)
void attn_mma()
{
    __shared__ __align__(16) __nv_bfloat16 Kh[64 * 72], Kl[64 * 72];
    __shared__ __align__(16) __nv_bfloat16 Vh[VROWS * 72], Vl[VROWS * 72];

    const int blh  = blockIdx.y;
    const int qblk = gridDim.x - 1 - blockIdx.x;   // heavy-first
    const int q0   = qblk * 128;
    const int tid  = threadIdx.x;
    const int warp = tid >> 5, lane = tid & 31;
    const int g = lane >> 2, t = lane & 3;

    // Q fragments (per warp, loaded once from gmem)
    u32 qa_h[4][4], qa_l[4][4];
    {
        const u32* qh = (const u32*)(g_qhi + ((size_t)blh * S_LEN + q0 + warp * 16) * DH);
        const u32* ql = (const u32*)(g_qlo + ((size_t)blh * S_LEN + q0 + warp * 16) * DH);
        #pragma unroll
        for (int k = 0; k < 4; k++) {
            qa_h[k][0] = qh[(g)     * 32 + k * 8 + t];
            qa_h[k][1] = qh[(g + 8) * 32 + k * 8 + t];
            qa_h[k][2] = qh[(g)     * 32 + k * 8 + 4 + t];
            qa_h[k][3] = qh[(g + 8) * 32 + k * 8 + 4 + t];
            qa_l[k][0] = ql[(g)     * 32 + k * 8 + t];
            qa_l[k][1] = ql[(g + 8) * 32 + k * 8 + t];
            qa_l[k][2] = ql[(g)     * 32 + k * 8 + 4 + t];
            qa_l[k][3] = ql[(g + 8) * 32 + k * 8 + 4 + t];
        }
    }

    float accO[9][4];
    #pragma unroll
    for (int j = 0; j < 9; j++)
        #pragma unroll
        for (int d = 0; d < 4; d++) accO[j][d] = 0.f;

    const int rmin  = q0 + warp * 16;
    const int kbmax = (q0 + 127) >> 6;

    const __nv_bfloat16* Kbh = g_khi + (size_t)blh * S_LEN * DH;
    const __nv_bfloat16* Kbl = g_klo + (size_t)blh * S_LEN * DH;
    const __nv_bfloat16* Vbh = g_vthi + (size_t)blh * VROWS * S_LEN;
    const __nv_bfloat16* Vbl = g_vtlo + (size_t)blh * VROWS * S_LEN;

    for (int kb = 0; kb <= kbmax; kb++) {
        __syncthreads();
        // K tile: 64 x 64 halves (pad rows to 72)
        #pragma unroll
        for (int i = 0; i < 2; i++) {
            int idx = i * 256 + tid;
            int row = idx >> 3, c = idx & 7;
            ((uint4*)Kh)[row * 9 + c] =
                *(const uint4*)(Kbh + (size_t)(kb * 64 + row) * DH + c * 8);
            ((uint4*)Kl)[row * 9 + c] =
                *(const uint4*)(Kbl + (size_t)(kb * 64 + row) * DH + c * 8);
        }
        // V^T tile: 72 x 64 halves
        #pragma unroll
        for (int i = 0; i < 3; i++) {
            int idx = i * 256 + tid;
            if (idx < 576) {
                int row = idx >> 3, c = idx & 7;
                ((uint4*)Vh)[row * 9 + c] =
                    *(const uint4*)(Vbh + (size_t)row * S_LEN + kb * 64 + c * 8);
                ((uint4*)Vl)[row * 9 + c] =
                    *(const uint4*)(Vbl + (size_t)row * S_LEN + kb * 64 + c * 8);
            }
        }
        __syncthreads();

        if (kb * 64 > rmin + 15) continue;   // fully-masked for this warp

        // ---- S = Q K^T (3-term split) ----
        float s[8][4];
        #pragma unroll
        for (int j = 0; j < 8; j++)
            #pragma unroll
            for (int d = 0; d < 4; d++) s[j][d] = 0.f;

        const u32* Kh32 = (const u32*)Kh;
        const u32* Kl32 = (const u32*)Kl;
        #pragma unroll
        for (int k = 0; k < 4; k++)
            #pragma unroll
            for (int j = 0; j < 8; j++) {
                u32 off = (8 * j + g) * 36 + k * 8 + t;
                u32 b0h = Kh32[off], b1h = Kh32[off + 4];
                u32 b0l = Kl32[off], b1l = Kl32[off + 4];
                mmab(s[j], qa_h[k], b0h, b1h);
                mmab(s[j], qa_h[k], b0l, b1l);
                mmab(s[j], qa_l[k], b0h, b1h);
            }

        // ---- softmax (no max) + in-register P fragment build ----
        u32 pa_h[4][4], pa_l[4][4];
        const bool diag = (kb * 64 + 63 > rmin);
        #pragma unroll
        for (int j = 0; j < 8; j++) {
            float p0 = __expf(s[j][0]);
            float p1 = __expf(s[j][1]);
            float p2 = __expf(s[j][2]);
            float p3 = __expf(s[j][3]);
            if (diag) {
                int c0 = kb * 64 + 8 * j + 2 * t;
                int r0 = rmin + g, r1 = r0 + 8;
                if (c0     > r0) p0 = 0.f;
                if (c0 + 1 > r0) p1 = 0.f;
                if (c0     > r1) p2 = 0.f;
                if (c0 + 1 > r1) p3 = 0.f;
            }
            float h0 = bfr(p0), h1 = bfr(p1), h2 = bfr(p2), h3 = bfr(p3);
            int kk = j >> 1, hh = (j & 1) * 2;
            pa_h[kk][hh]     = pkbf(h0, h1);
            pa_h[kk][hh + 1] = pkbf(h2, h3);
            pa_l[kk][hh]     = pkbf(p0 - h0, p1 - h1);
            pa_l[kk][hh + 1] = pkbf(p2 - h2, p3 - h3);
        }

        // ---- O += P V (3-term split); ones-column accumulates row sums ----
        const u32* Vh32 = (const u32*)Vh;
        const u32* Vl32 = (const u32*)Vl;
        #pragma unroll
        for (int k = 0; k < 4; k++)
            #pragma unroll
            for (int j = 0; j < 9; j++) {
                u32 off = (8 * j + g) * 36 + k * 8 + t;
                u32 b0h = Vh32[off], b1h = Vh32[off + 4];
                u32 b0l = Vl32[off], b1l = Vl32[off + 4];
                mmab(accO[j], pa_h[k], b0h, b1h);
                mmab(accO[j], pa_h[k], b0l, b1l);
                mmab(accO[j], pa_l[k], b0h, b1h);
            }
    }

    // ---- finalize: divide by row sums (col 64), split, store inter ----
    float l0 = __shfl_sync(0xffffffffu, accO[8][0], lane & ~3);
    float l1 = __shfl_sync(0xffffffffu, accO[8][2], lane & ~3);
    float inv0 = 1.f / l0, inv1 = 1.f / l1;

    const int bl = blh >> 3, h = blh & 7;
    const int r0 = q0 + warp * 16 + g;
    u32* ih = (u32*)g_ihi;
    u32* il = (u32*)g_ilo;
    #pragma unroll
    for (int j = 0; j < 8; j++) {
        int c = h * DH + 8 * j + 2 * t;
        float o0 = accO[j][0] * inv0, o1 = accO[j][1] * inv0;
        float o2 = accO[j][2] * inv1, o3 = accO[j][3] * inv1;
        float h0 = bfr(o0), h1 = bfr(o1), h2 = bfr(o2), h3 = bfr(o3);
        size_t i0 = ((size_t)(bl * S_LEN + r0)) * 256 + (c >> 1);
        size_t i1 = ((size_t)(bl * S_LEN + r0 + 8)) * 256 + (c >> 1);
        ih[i0] = pkbf(h0, h1);
        il[i0] = pkbf(o0 - h0, o1 - h1);
        ih[i1] = pkbf(h2, h3);
        il[i1] = pkbf(o2 - h2, o3 - h3);
    }
}

// ---------------------------------------------------------------------------
extern "C" void kernel_launch(void* const* d_in, const int* in_sizes, int n_in,
                              void* d_out, int out_size)
{
    const float* x  = (const float*)d_in[0];
    const float* Wq = (const float*)d_in[1];
    const float* bq = (const float*)d_in[2];
    const float* Wk = (const float*)d_in[3];
    const float* bk = (const float*)d_in[4];
    const float* Wv = (const float*)d_in[5];
    const float* bv = (const float*)d_in[6];
    const float* Wo = (const float*)d_in[7];
    const float* bo = (const float*)d_in[8];
    float* out = (float*)d_out;

    __nv_bfloat16 *xhi, *xlo, *whi, *wlo;
    cudaGetSymbolAddress((void**)&xhi, g_xhi);
    cudaGetSymbolAddress((void**)&xlo, g_xlo);
    cudaGetSymbolAddress((void**)&whi, g_whi);
    cudaGetSymbolAddress((void**)&wlo, g_wlo);

    const int WN = DIMN * DIMN;          // 262144

    split_kernel<<<MTOT * DIMN / 256, 256>>>(x, xhi, xlo);
    split_kernel<<<WN / 256, 256>>>(Wq, whi + 0 * WN, wlo + 0 * WN);
    split_kernel<<<WN / 256, 256>>>(Wk, whi + 1 * WN, wlo + 1 * WN);
    split_kernel<<<WN / 256, 256>>>(Wv, whi + 2 * WN, wlo + 2 * WN);
    split_kernel<<<WN / 256, 256>>>(Wo, whi + 3 * WN, wlo + 3 * WN);
    vt_ones_kernel<<<NBLH * 8 * S_LEN / 256, 256>>>();

    dim3 gg(DIMN / 64, MTOT / 128);      // (8, 64)
    // Reference quirks: q = rotary(x@Wq^T), k = rotary(x@Wv^T), v = x@Wk^T
    mma_gemm<<<gg, 256>>>(bq, nullptr, 0, 0, 1, QSCALE, 0);  // Q (scaled, rotary)
    mma_gemm<<<gg, 256>>>(bv, nullptr, 2, 1, 1, 1.0f, 0);    // K from Wv (rotary)
    mma_gemm<<<gg, 256>>>(bk, nullptr, 1, 2, 0, 1.0f, 0);    // V from Wk -> V^T

    attn_mma<<<dim3(S_LEN / 128, NBLH), 256>>>();

    mma_gemm<<<gg, 256>>>(bo, out, 3, 3, 0, 1.0f, 1);        // inter @ Wo^T + bo
}

// round 5
// speedup vs baseline: 3.1155x; 1.1779x over previous
#include <cuda_runtime.h>
#include <cuda_bf16.h>

typedef unsigned int u32;

#define S_LEN 2048
#define DIMN  512
#define NH    8
#define DH    64
#define MTOT  8192
#define NBLH  32
#define VROWS 80          // 64 d-rows + ones row (64) + 15 zero pad rows
#define QSCALE 0.04419417382415922f   // 1/sqrt(512)
#define LNC 0.14391156831212787f      // ln(10000)/64

// ---------------------------------------------------------------------------
// Scratch (allocation-free device globals), bf16 hi/lo pairs
// ---------------------------------------------------------------------------
__device__ __align__(16) __nv_bfloat16 g_xhi[MTOT * DIMN],  g_xlo[MTOT * DIMN];
__device__ __align__(16) __nv_bfloat16 g_whi[4 * DIMN * DIMN], g_wlo[4 * DIMN * DIMN];
__device__ __align__(16) __nv_bfloat16 g_qhi[NBLH * S_LEN * DH], g_qlo[NBLH * S_LEN * DH];
__device__ __align__(16) __nv_bfloat16 g_khi[NBLH * S_LEN * DH], g_klo[NBLH * S_LEN * DH];
__device__ __align__(16) __nv_bfloat16 g_vthi[NBLH * VROWS * S_LEN], g_vtlo[NBLH * VROWS * S_LEN];
__device__ __align__(16) __nv_bfloat16 g_ihi[MTOT * DIMN],  g_ilo[MTOT * DIMN];

// ---------------------------------------------------------------------------
// Helpers
// ---------------------------------------------------------------------------
__device__ __forceinline__ u32 pkbf(float a, float b) {   // a->lo, b->hi
    u32 r;
    asm("cvt.rn.bf16x2.f32 %0, %1, %2;" : "=r"(r) : "f"(b), "f"(a));
    return r;
}
__device__ __forceinline__ float bfr(float v) {
    return __bfloat162float(__float2bfloat16(v));
}
__device__ __forceinline__ void mmab(float* d, const u32* a, u32 b0, u32 b1) {
    asm volatile(
        "mma.sync.aligned.m16n8k16.row.col.f32.bf16.bf16.f32 "
        "{%0,%1,%2,%3}, {%4,%5,%6,%7}, {%8,%9}, {%0,%1,%2,%3};"
        : "+f"(d[0]), "+f"(d[1]), "+f"(d[2]), "+f"(d[3])
        : "r"(a[0]), "r"(a[1]), "r"(a[2]), "r"(a[3]), "r"(b0), "r"(b1));
}
__device__ __forceinline__ u32 smem_u32(const void* p) {
    u32 a;
    asm("{ .reg .u64 t; cvta.to.shared.u64 t, %1; cvt.u32.u64 %0, t; }"
        : "=r"(a) : "l"(p));
    return a;
}
__device__ __forceinline__ void cpa16(u32 dst, const void* src) {
    asm volatile("cp.async.cg.shared.global [%0], [%1], 16;" :: "r"(dst), "l"(src));
}
__device__ __forceinline__ void cpcommit() {
    asm volatile("cp.async.commit_group;" ::: "memory");
}
__device__ __forceinline__ void cpwait1() {
    asm volatile("cp.async.wait_group 1;" ::: "memory");
}
__device__ __forceinline__ void cpwait0() {
    asm volatile("cp.async.wait_group 0;" ::: "memory");
}
__device__ __forceinline__ void ldsm4(u32* r, u32 a) {
    asm volatile("ldmatrix.sync.aligned.m8n8.x4.shared.b16 {%0,%1,%2,%3}, [%4];"
                 : "=r"(r[0]), "=r"(r[1]), "=r"(r[2]), "=r"(r[3]) : "r"(a));
}

// ---------------------------------------------------------------------------
// Split fp32 -> bf16 hi/lo
// ---------------------------------------------------------------------------
__global__ __launch_bounds__(256)
void split_kernel(const float* __restrict__ src,
                  __nv_bfloat16* __restrict__ hi,
                  __nv_bfloat16* __restrict__ lo)
{
    int i = blockIdx.x * 256 + threadIdx.x;
    float v = src[i];
    __nv_bfloat16 h = __float2bfloat16(v);
    hi[i] = h;
    lo[i] = __float2bfloat16(v - __bfloat162float(h));
}

// Fill V^T rows 64..79 (ones row + zero pad) for all heads
__global__ __launch_bounds__(256)
void vt_ones_kernel()
{
    int idx = blockIdx.x * 256 + threadIdx.x;     // 32*16*2048 total
    int s   = idx & (S_LEN - 1);
    int rr  = (idx >> 11) & 15;
    int blh = idx >> 15;
    size_t a = ((size_t)blh * VROWS + 64 + rr) * S_LEN + s;
    g_vthi[a] = __float2bfloat16(rr == 0 ? 1.0f : 0.0f);
    g_vtlo[a] = __float2bfloat16(0.0f);
}

// ---------------------------------------------------------------------------
// MMA GEMM: Y[m][e] = sum_d A[m][d]*W[e][d] + bias[e] (split-bf16, 3 MMAs).
// Tile M=128, N=64, k-step 32, double-buffered cp.async, ldmatrix fragments.
// dst_sel: 0 Q(blh,s,dh)  1 K(blh,s,dh)  2 V^T(blh,80,s)  3 fp32 out(m,512)
// ---------------------------------------------------------------------------
#define GSTAGE_B 30720     // bytes per stage (15360 halves)
__global__ __launch_bounds__(256, 1)
void mma_gemm(const float* __restrict__ bias,
              float* __restrict__ outp,
              int widx, int dst_sel, int do_rot, float scale, int src_sel)
{
    extern __shared__ __align__(16) __nv_bfloat16 dsm[];
    // stage layout (bytes): Ah 0 (128x40h), Al 10240, Wh 20480 (64x40h), Wl 25600

    const __nv_bfloat16* Ahg = src_sel ? g_ihi : g_xhi;
    const __nv_bfloat16* Alg = src_sel ? g_ilo : g_xlo;
    const __nv_bfloat16* Whg = g_whi + (size_t)widx * DIMN * DIMN;
    const __nv_bfloat16* Wlg = g_wlo + (size_t)widx * DIMN * DIMN;

    const int n0 = blockIdx.x * 64;
    const int m0 = blockIdx.y * 128;
    const int tid = threadIdx.x;
    const int warp = tid >> 5, lane = tid & 31;
    const int g = lane >> 2, t = lane & 3;
    const u32 smb = smem_u32(dsm);

    // ldmatrix per-lane row/col offsets
    const int rA = ((lane >> 3) & 1) * 8 + (lane & 7);
    const int cA = ((lane >> 4) & 1) * 8;
    const int rB = (lane >> 4) * 8 + (lane & 7);
    const int cB = ((lane >> 3) & 1) * 8;

    float acc[8][4];
    #pragma unroll
    for (int j = 0; j < 8; j++)
        #pragma unroll
        for (int d = 0; d < 4; d++) acc[j][d] = 0.f;

    // ---- prefetch stage ----
    auto prefetch = [&](int kt, int st) {
        u32 sb = smb + st * GSTAGE_B;
        int k0 = kt * 32;
        #pragma unroll
        for (int i = 0; i < 2; i++) {
            int idx = i * 256 + tid;
            int row = idx >> 2, c = idx & 3;
            cpa16(sb + (row * 40 + c * 8) * 2,
                  Ahg + (size_t)(m0 + row) * DIMN + k0 + c * 8);
            cpa16(sb + 10240 + (row * 40 + c * 8) * 2,
                  Alg + (size_t)(m0 + row) * DIMN + k0 + c * 8);
        }
        {
            int row = tid >> 2, c = tid & 3;
            cpa16(sb + 20480 + (row * 40 + c * 8) * 2,
                  Whg + (size_t)(n0 + row) * DIMN + k0 + c * 8);
            cpa16(sb + 25600 + (row * 40 + c * 8) * 2,
                  Wlg + (size_t)(n0 + row) * DIMN + k0 + c * 8);
        }
        cpcommit();
    };

    prefetch(0, 0);

    for (int kt = 0; kt < 16; kt++) {
        int st = kt & 1;
        __syncthreads();
        if (kt < 15) { prefetch(kt + 1, st ^ 1); cpwait1(); }
        else         { cpwait0(); }
        __syncthreads();

        u32 sb = smb + st * GSTAGE_B;
        u32 aH = sb + ((warp * 16 + rA) * 40 + cA) * 2;
        u32 aL = aH + 10240;
        u32 bH = sb + 20480 + (rB * 40 + cB) * 2;
        u32 bL = bH + 5120;

        #pragma unroll
        for (int kk = 0; kk < 2; kk++) {
            u32 ah[4], al[4];
            ldsm4(ah, aH + kk * 32);
            ldsm4(al, aL + kk * 32);
            #pragma unroll
            for (int j2 = 0; j2 < 4; j2++) {
                u32 bh[4], bl[4];
                ldsm4(bh, bH + j2 * (16 * 40 * 2) + kk * 32);
                ldsm4(bl, bL + j2 * (16 * 40 * 2) + kk * 32);
                mmab(acc[2 * j2],     ah, bh[0], bh[1]);
                mmab(acc[2 * j2],     ah, bl[0], bl[1]);
                mmab(acc[2 * j2],     al, bh[0], bh[1]);
                mmab(acc[2 * j2 + 1], ah, bh[2], bh[3]);
                mmab(acc[2 * j2 + 1], ah, bl[2], bl[3]);
                mmab(acc[2 * j2 + 1], al, bh[2], bh[3]);
            }
        }
    }

    // ---- Epilogue ----
    const int rb = warp * 16;

    if (dst_sel == 2) {
        // V^T: transpose via smem (two passes: hi then lo)
        __nv_bfloat16* T = dsm;   // 64 x 136
        const int bl = m0 >> 11, hh = n0 >> 6;
        const int s0 = m0 & (S_LEN - 1);
        #pragma unroll
        for (int pass = 0; pass < 2; pass++) {
            __syncthreads();
            #pragma unroll
            for (int j = 0; j < 8; j++) {
                int cl0 = 8 * j + 2 * t;
                float b0 = bias[n0 + cl0], b1 = bias[n0 + cl0 + 1];
                float v00 = acc[j][0] + b0, v01 = acc[j][1] + b1;
                float v10 = acc[j][2] + b0, v11 = acc[j][3] + b1;
                float e00, e01, e10, e11;
                if (pass == 0) { e00 = v00; e01 = v01; e10 = v10; e11 = v11; }
                else { e00 = v00 - bfr(v00); e01 = v01 - bfr(v01);
                       e10 = v10 - bfr(v10); e11 = v11 - bfr(v11); }
                T[(cl0)     * 136 + rb + g]     = __float2bfloat16(e00);
                T[(cl0 + 1) * 136 + rb + g]     = __float2bfloat16(e01);
                T[(cl0)     * 136 + rb + g + 8] = __float2bfloat16(e10);
                T[(cl0 + 1) * 136 + rb + g + 8] = __float2bfloat16(e11);
            }
            __syncthreads();
            __nv_bfloat16* dst = pass ? g_vtlo : g_vthi;
            size_t base = ((size_t)(bl * NH + hh)) * VROWS * S_LEN + s0;
            #pragma unroll
            for (int w8 = 0; w8 < 4; w8++) {
                int idx = w8 * 256 + tid;
                int row = idx >> 4, c8 = idx & 15;
                *(uint4*)(dst + base + (size_t)row * S_LEN + c8 * 8) =
                    *(const uint4*)(T + row * 136 + c8 * 8);
            }
        }
        return;
    }

    #pragma unroll
    for (int j = 0; j < 8; j++) {
        int c0 = n0 + 8 * j + 2 * t;
        float b0 = bias[c0], b1 = bias[c0 + 1];
        float v00 = acc[j][0] + b0, v01 = acc[j][1] + b1;
        float v10 = acc[j][2] + b0, v11 = acc[j][3] + b1;
        int r0 = m0 + rb + g, r1 = r0 + 8;
        if (do_rot) {
            float invf = expf(-(float)(c0 & (DH - 1)) * LNC);
            float sn, cs;
            sincosf((float)(r0 & (S_LEN - 1)) * invf, &sn, &cs);
            float x0 = v00, x1 = v01;
            v00 = x0 * cs - x1 * sn;  v01 = x1 * cs + x0 * sn;
            sincosf((float)(r1 & (S_LEN - 1)) * invf, &sn, &cs);
            x0 = v10; x1 = v11;
            v10 = x0 * cs - x1 * sn;  v11 = x1 * cs + x0 * sn;
        }
        v00 *= scale; v01 *= scale; v10 *= scale; v11 *= scale;

        if (dst_sel == 3) {
            *(float2*)(outp + (size_t)r0 * DIMN + c0) = make_float2(v00, v01);
            *(float2*)(outp + (size_t)r1 * DIMN + c0) = make_float2(v10, v11);
        } else {
            u32* dh = (u32*)(dst_sel ? g_khi : g_qhi);
            u32* dl = (u32*)(dst_sel ? g_klo : g_qlo);
            int hh = c0 >> 6, jd = c0 & (DH - 1);
            int bl = m0 >> 11;
            size_t i0 = (((size_t)(bl * NH + hh) * S_LEN + (r0 & (S_LEN - 1))) * DH + jd) >> 1;
            size_t i1 = (((size_t)(bl * NH + hh) * S_LEN + (r1 & (S_LEN - 1))) * DH + jd) >> 1;
            float h00 = bfr(v00), h01 = bfr(v01), h10 = bfr(v10), h11 = bfr(v11);
            dh[i0] = pkbf(h00, h01);
            dl[i0] = pkbf(v00 - h00, v01 - h01);
            dh[i1] = pkbf(h10, h11);
            dl[i1] = pkbf(v10 - h10, v11 - h11);
        }
    }
}

// ---------------------------------------------------------------------------
// Flash attention via HMMA, causal, no-max softmax, ones-column row sums.
// Double-buffered cp.async staging, ldmatrix fragments.
// Block = 128 q rows of one (bl,h); 256 threads = 8 warps, warp owns m16.
// ---------------------------------------------------------------------------
#define ASTAGE_B 41472     // bytes per stage: Kh 0, Kl 9216, Vh 18432, Vl 29952
__global__ __launch_bounds__(256, 1)
void attn_mma()
{
    extern __shared__ __align__(16) __nv_bfloat16 dsm[];

    const int blh  = blockIdx.y;
    const int qblk = gridDim.x - 1 - blockIdx.x;   // heavy-first
    const int q0   = qblk * 128;
    const int tid  = threadIdx.x;
    const int warp = tid >> 5, lane = tid & 31;
    const int g = lane >> 2, t = lane & 3;
    const u32 smb = smem_u32(dsm);

    const int rB = (lane >> 4) * 8 + (lane & 7);
    const int cB = ((lane >> 3) & 1) * 8;

    const __nv_bfloat16* Kbh = g_khi + (size_t)blh * S_LEN * DH;
    const __nv_bfloat16* Kbl = g_klo + (size_t)blh * S_LEN * DH;
    const __nv_bfloat16* Vbh = g_vthi + (size_t)blh * VROWS * S_LEN;
    const __nv_bfloat16* Vbl = g_vtlo + (size_t)blh * VROWS * S_LEN;

    // Q fragments (per warp, loaded once from gmem)
    u32 qa_h[4][4], qa_l[4][4];
    {
        const u32* qh = (const u32*)(g_qhi + ((size_t)blh * S_LEN + q0 + warp * 16) * DH);
        const u32* ql = (const u32*)(g_qlo + ((size_t)blh * S_LEN + q0 + warp * 16) * DH);
        #pragma unroll
        for (int k = 0; k < 4; k++) {
            qa_h[k][0] = qh[(g)     * 32 + k * 8 + t];
            qa_h[k][1] = qh[(g + 8) * 32 + k * 8 + t];
            qa_h[k][2] = qh[(g)     * 32 + k * 8 + 4 + t];
            qa_h[k][3] = qh[(g + 8) * 32 + k * 8 + 4 + t];
            qa_l[k][0] = ql[(g)     * 32 + k * 8 + t];
            qa_l[k][1] = ql[(g + 8) * 32 + k * 8 + t];
            qa_l[k][2] = ql[(g)     * 32 + k * 8 + 4 + t];
            qa_l[k][3] = ql[(g + 8) * 32 + k * 8 + 4 + t];
        }
    }

    float accO[9][4];
    #pragma unroll
    for (int j = 0; j < 9; j++)
        #pragma unroll
        for (int d = 0; d < 4; d++) accO[j][d] = 0.f;

    const int rmin  = q0 + warp * 16;
    const int kbmax = (q0 + 127) >> 6;

    auto prefetch = [&](int kb, int st) {
        u32 sb = smb + st * ASTAGE_B;
        #pragma unroll
        for (int i = 0; i < 2; i++) {
            int idx = i * 256 + tid;
            int row = idx >> 3, c = idx & 7;
            cpa16(sb + (row * 72 + c * 8) * 2,
                  Kbh + (size_t)(kb * 64 + row) * DH + c * 8);
            cpa16(sb + 9216 + (row * 72 + c * 8) * 2,
                  Kbl + (size_t)(kb * 64 + row) * DH + c * 8);
        }
        #pragma unroll
        for (int i = 0; i < 3; i++) {
            int idx = i * 256 + tid;
            if (idx < 640) {
                int row = idx >> 3, c = idx & 7;
                cpa16(sb + 18432 + (row * 72 + c * 8) * 2,
                      Vbh + (size_t)row * S_LEN + kb * 64 + c * 8);
                cpa16(sb + 29952 + (row * 72 + c * 8) * 2,
                      Vbl + (size_t)row * S_LEN + kb * 64 + c * 8);
            }
        }
        cpcommit();
    };

    prefetch(0, 0);

    for (int kb = 0; kb <= kbmax; kb++) {
        int st = kb & 1;
        __syncthreads();
        if (kb < kbmax) { prefetch(kb + 1, st ^ 1); cpwait1(); }
        else            { cpwait0(); }
        __syncthreads();

        if (kb * 64 > rmin + 15) continue;   // fully-masked for this warp

        u32 sb = smb + st * ASTAGE_B;
        u32 kH = sb + (rB * 72 + cB) * 2;
        u32 kL = kH + 9216;
        u32 vH = sb + 18432 + (rB * 72 + cB) * 2;
        u32 vL = vH + 11520;

        // ---- S = Q K^T (3-term split) ----
        float s[8][4];
        #pragma unroll
        for (int j = 0; j < 8; j++)
            #pragma unroll
            for (int d = 0; d < 4; d++) s[j][d] = 0.f;

        #pragma unroll
        for (int kk = 0; kk < 4; kk++)
            #pragma unroll
            for (int j2 = 0; j2 < 4; j2++) {
                u32 bh[4], bl[4];
                ldsm4(bh, kH + j2 * (16 * 72 * 2) + kk * 32);
                ldsm4(bl, kL + j2 * (16 * 72 * 2) + kk * 32);
                mmab(s[2 * j2],     qa_h[kk], bh[0], bh[1]);
                mmab(s[2 * j2],     qa_h[kk], bl[0], bl[1]);
                mmab(s[2 * j2],     qa_l[kk], bh[0], bh[1]);
                mmab(s[2 * j2 + 1], qa_h[kk], bh[2], bh[3]);
                mmab(s[2 * j2 + 1], qa_h[kk], bl[2], bl[3]);
                mmab(s[2 * j2 + 1], qa_l[kk], bh[2], bh[3]);
            }

        // ---- softmax (no max) + in-register P fragment build ----
        u32 pa_h[4][4], pa_l[4][4];
        const bool diag = (kb * 64 + 63 > rmin);
        #pragma unroll
        for (int j = 0; j < 8; j++) {
            float p0 = __expf(s[j][0]);
            float p1 = __expf(s[j][1]);
            float p2 = __expf(s[j][2]);
            float p3 = __expf(s[j][3]);
            if (diag) {
                int c0 = kb * 64 + 8 * j + 2 * t;
                int r0 = rmin + g, r1 = r0 + 8;
                if (c0     > r0) p0 = 0.f;
                if (c0 + 1 > r0) p1 = 0.f;
                if (c0     > r1) p2 = 0.f;
                if (c0 + 1 > r1) p3 = 0.f;
            }
            float h0 = bfr(p0), h1 = bfr(p1), h2 = bfr(p2), h3 = bfr(p3);
            int kk = j >> 1, hh = (j & 1) * 2;
            pa_h[kk][hh]     = pkbf(h0, h1);
            pa_h[kk][hh + 1] = pkbf(h2, h3);
            pa_l[kk][hh]     = pkbf(p0 - h0, p1 - h1);
            pa_l[kk][hh + 1] = pkbf(p2 - h2, p3 - h3);
        }

        // ---- O += P V (3-term split); ones-column accumulates row sums ----
        #pragma unroll
        for (int kk = 0; kk < 4; kk++)
            #pragma unroll
            for (int j2 = 0; j2 < 5; j2++) {
                u32 vh[4], vl[4];
                ldsm4(vh, vH + j2 * (16 * 72 * 2) + kk * 32);
                ldsm4(vl, vL + j2 * (16 * 72 * 2) + kk * 32);
                mmab(accO[2 * j2], pa_h[kk], vh[0], vh[1]);
                mmab(accO[2 * j2], pa_h[kk], vl[0], vl[1]);
                mmab(accO[2 * j2], pa_l[kk], vh[0], vh[1]);
                if (j2 < 4) {
                    mmab(accO[2 * j2 + 1], pa_h[kk], vh[2], vh[3]);
                    mmab(accO[2 * j2 + 1], pa_h[kk], vl[2], vl[3]);
                    mmab(accO[2 * j2 + 1], pa_l[kk], vh[2], vh[3]);
                }
            }
    }

    // ---- finalize: divide by row sums (frag j=8, n=64), split, store ----
    float l0 = __shfl_sync(0xffffffffu, accO[8][0], lane & ~3);
    float l1 = __shfl_sync(0xffffffffu, accO[8][2], lane & ~3);
    float inv0 = 1.f / l0, inv1 = 1.f / l1;

    const int bl = blh >> 3, h = blh & 7;
    const int r0 = q0 + warp * 16 + g;
    u32* ih = (u32*)g_ihi;
    u32* il = (u32*)g_ilo;
    #pragma unroll
    for (int j = 0; j < 8; j++) {
        int c = h * DH + 8 * j + 2 * t;
        float o0 = accO[j][0] * inv0, o1 = accO[j][1] * inv0;
        float o2 = accO[j][2] * inv1, o3 = accO[j][3] * inv1;
        float h0 = bfr(o0), h1 = bfr(o1), h2 = bfr(o2), h3 = bfr(o3);
        size_t i0 = ((size_t)(bl * S_LEN + r0)) * 256 + (c >> 1);
        size_t i1 = ((size_t)(bl * S_LEN + r0 + 8)) * 256 + (c >> 1);
        ih[i0] = pkbf(h0, h1);
        il[i0] = pkbf(o0 - h0, o1 - h1);
        ih[i1] = pkbf(h2, h3);
        il[i1] = pkbf(o2 - h2, o3 - h3);
    }
}

// ---------------------------------------------------------------------------
extern "C" void kernel_launch(void* const* d_in, const int* in_sizes, int n_in,
                              void* d_out, int out_size)
{
    const float* x  = (const float*)d_in[0];
    const float* Wq = (const float*)d_in[1];
    const float* bq = (const float*)d_in[2];
    const float* Wk = (const float*)d_in[3];
    const float* bk = (const float*)d_in[4];
    const float* Wv = (const float*)d_in[5];
    const float* bv = (const float*)d_in[6];
    const float* Wo = (const float*)d_in[7];
    const float* bo = (const float*)d_in[8];
    float* out = (float*)d_out;

    __nv_bfloat16 *xhi, *xlo, *whi, *wlo;
    cudaGetSymbolAddress((void**)&xhi, g_xhi);
    cudaGetSymbolAddress((void**)&xlo, g_xlo);
    cudaGetSymbolAddress((void**)&whi, g_whi);
    cudaGetSymbolAddress((void**)&wlo, g_wlo);

    cudaFuncSetAttribute(mma_gemm, cudaFuncAttributeMaxDynamicSharedMemorySize,
                         2 * GSTAGE_B);
    cudaFuncSetAttribute(attn_mma, cudaFuncAttributeMaxDynamicSharedMemorySize,
                         2 * ASTAGE_B);

    const int WN = DIMN * DIMN;

    split_kernel<<<MTOT * DIMN / 256, 256>>>(x, xhi, xlo);
    split_kernel<<<WN / 256, 256>>>(Wq, whi + 0 * WN, wlo + 0 * WN);
    split_kernel<<<WN / 256, 256>>>(Wk, whi + 1 * WN, wlo + 1 * WN);
    split_kernel<<<WN / 256, 256>>>(Wv, whi + 2 * WN, wlo + 2 * WN);
    split_kernel<<<WN / 256, 256>>>(Wo, whi + 3 * WN, wlo + 3 * WN);
    vt_ones_kernel<<<NBLH * 16 * S_LEN / 256, 256>>>();

    dim3 gg(DIMN / 64, MTOT / 128);      // (8, 64)
    // Reference quirks: q = rotary(x@Wq^T), k = rotary(x@Wv^T), v = x@Wk^T
    mma_gemm<<<gg, 256, 2 * GSTAGE_B>>>(bq, nullptr, 0, 0, 1, QSCALE, 0);
    mma_gemm<<<gg, 256, 2 * GSTAGE_B>>>(bv, nullptr, 2, 1, 1, 1.0f, 0);
    mma_gemm<<<gg, 256, 2 * GSTAGE_B>>>(bk, nullptr, 1, 2, 0, 1.0f, 0);

    attn_mma<<<dim3(S_LEN / 128, NBLH), 256, 2 * ASTAGE_B>>>();

    mma_gemm<<<gg, 256, 2 * GSTAGE_B>>>(bo, out, 3, 3, 0, 1.0f, 1);
}